// round 1
// baseline (speedup 1.0000x reference)
#include <cuda_runtime.h>

// Problem constants
#define Bz   4
#define Nseq 2048
#define Cdim 1024
#define Hn   16
#define Dh   64
#define BHn  (Bz * Hn)

// Scratch (device globals — no runtime allocation allowed)
__device__ float g_q[(size_t)BHn * Nseq * Dh];   // [b,h,n,d] 32 MB
__device__ float g_k[(size_t)BHn * Nseq * Dh];
__device__ float g_v[(size_t)BHn * Nseq * Dh];
__device__ float g_y[(size_t)Bz * Nseq * Cdim];  // [b,n,c] 32 MB

// ---------------------------------------------------------------------------
// SGEMM: C[M,N] = A[M,K] @ B[K,N], row-major. 128x128 tile, BK=16, 256 thr,
// 8x8 microtile per thread.
// MODE 0: A = x, epilogue scatters into g_q/g_k/g_v ([b,h,n,d], fold split+transpose)
// MODE 1: A = g_y (param ignored), epilogue writes C row-major (final output)
// ---------------------------------------------------------------------------
template <int MODE>
__global__ __launch_bounds__(256)
void sgemm_kernel(const float* __restrict__ Ain, const float* __restrict__ Bm,
                  float* __restrict__ Cout, int M, int Nn, int K)
{
    const float* A = (MODE == 1) ? g_y : Ain;
    __shared__ float As[16][128];   // transposed A tile: As[k][m]
    __shared__ float Bs[16][128];   // Bs[k][n]

    const int tid = threadIdx.x;
    const int tx  = tid & 15;       // 16 col-groups
    const int ty  = tid >> 4;       // 16 row-groups
    const int bM  = blockIdx.y * 128;
    const int bN  = blockIdx.x * 128;

    float acc[8][8];
#pragma unroll
    for (int i = 0; i < 8; i++)
#pragma unroll
        for (int j = 0; j < 8; j++) acc[i][j] = 0.f;

    for (int k0 = 0; k0 < K; k0 += 16) {
        // Load A tile 128x16 (512 float4), transpose into As
#pragma unroll
        for (int i = 0; i < 2; i++) {
            int e = tid + i * 256;
            int row = e >> 2, c4 = e & 3;
            float4 v = *(const float4*)(A + (size_t)(bM + row) * K + k0 + c4 * 4);
            As[c4 * 4 + 0][row] = v.x;
            As[c4 * 4 + 1][row] = v.y;
            As[c4 * 4 + 2][row] = v.z;
            As[c4 * 4 + 3][row] = v.w;
        }
        // Load B tile 16x128 (512 float4)
#pragma unroll
        for (int i = 0; i < 2; i++) {
            int e = tid + i * 256;
            int row = e >> 5, c4 = e & 31;
            *(float4*)&Bs[row][c4 * 4] =
                *(const float4*)(Bm + (size_t)(k0 + row) * Nn + bN + c4 * 4);
        }
        __syncthreads();

#pragma unroll
        for (int k = 0; k < 16; k++) {
            float a[8], b[8];
            *(float4*)&a[0] = *(const float4*)&As[k][ty * 8];
            *(float4*)&a[4] = *(const float4*)&As[k][ty * 8 + 4];
            *(float4*)&b[0] = *(const float4*)&Bs[k][tx * 8];
            *(float4*)&b[4] = *(const float4*)&Bs[k][tx * 8 + 4];
#pragma unroll
            for (int i = 0; i < 8; i++)
#pragma unroll
                for (int j = 0; j < 8; j++)
                    acc[i][j] += a[i] * b[j];
        }
        __syncthreads();
    }

    if (MODE == 0) {
        // f in [0,3072): sec = f/1024 -> q/k/v ; c = f%1024 ; h = c/64 ; d = c%64
        // q[b,h,n,d] = qkv[b,n, sec*1024 + h*64 + d]
#pragma unroll
        for (int i = 0; i < 8; i++) {
            int m  = bM + ty * 8 + i;
            int bb = m >> 11;            // / 2048
            int n  = m & (Nseq - 1);
#pragma unroll
            for (int j4 = 0; j4 < 8; j4 += 4) {
                int f   = bN + tx * 8 + j4;
                int sec = f >> 10;
                int c   = f & (Cdim - 1);
                int h   = c >> 6;
                int d   = c & 63;
                float* dst = (sec == 0) ? g_q : (sec == 1) ? g_k : g_v;
                float4 v = make_float4(acc[i][j4], acc[i][j4 + 1],
                                       acc[i][j4 + 2], acc[i][j4 + 3]);
                *(float4*)&dst[((size_t)(bb * Hn + h) * Nseq + n) * Dh + d] = v;
            }
        }
    } else {
#pragma unroll
        for (int i = 0; i < 8; i++) {
            int m = bM + ty * 8 + i;
            float* row = Cout + (size_t)m * Nn + bN + tx * 8;
            *(float4*)row       = make_float4(acc[i][0], acc[i][1], acc[i][2], acc[i][3]);
            *(float4*)(row + 4) = make_float4(acc[i][4], acc[i][5], acc[i][6], acc[i][7]);
        }
    }
}

// ---------------------------------------------------------------------------
// Flash attention: one block per (b*H + h, 64-query tile). 128 threads.
// Thread (rp = tid/4, cg = tid%4) owns rows {2rp, 2rp+1}, dims [cg*16, cg*16+16)
// Online softmax over 32-key inner tiles. Writes y[b,n,h*64+d] into g_y.
// ---------------------------------------------------------------------------
#define KT 32

__global__ __launch_bounds__(128)
void attn_kernel()
{
    __shared__ float Qs[64][64];
    __shared__ float Ks[KT][64];
    __shared__ float Vs[KT][64];
    __shared__ float Ps[64][KT + 1];   // +1 pad: conflict-free Ps[r][j] reads

    const int tid = threadIdx.x;
    const int bh  = blockIdx.y;
    const int q0  = blockIdx.x * 64;
    const int cg  = tid & 3;
    const int rp  = tid >> 2;
    const int r0  = rp * 2;

    const float* Qg = g_q + (size_t)bh * Nseq * Dh;
    const float* Kg = g_k + (size_t)bh * Nseq * Dh;
    const float* Vg = g_v + (size_t)bh * Nseq * Dh;

    // Load Q tile (fold softmax scale 1/sqrt(64) = 0.125 into Q)
#pragma unroll
    for (int i = 0; i < 8; i++) {
        int e = tid + i * 128;             // 1024 float4s
        int r = e >> 4, d4 = e & 15;
        float4 v = *(const float4*)(Qg + (size_t)(q0 + r) * Dh + d4 * 4);
        v.x *= 0.125f; v.y *= 0.125f; v.z *= 0.125f; v.w *= 0.125f;
        *(float4*)&Qs[r][d4 * 4] = v;
    }

    float m0 = -1e30f, m1 = -1e30f;
    float l0 = 0.f,    l1 = 0.f;
    float acc0[16], acc1[16];
#pragma unroll
    for (int i = 0; i < 16; i++) { acc0[i] = 0.f; acc1[i] = 0.f; }

    for (int j0 = 0; j0 < Nseq; j0 += KT) {
        __syncthreads();   // previous PV done with Ks/Vs (also orders Qs on iter 0)
#pragma unroll
        for (int i = 0; i < (KT * 16) / 128; i++) {
            int e = tid + i * 128;
            int r = e >> 4, d4 = e & 15;
            *(float4*)&Ks[r][d4 * 4] = *(const float4*)(Kg + (size_t)(j0 + r) * Dh + d4 * 4);
            *(float4*)&Vs[r][d4 * 4] = *(const float4*)(Vg + (size_t)(j0 + r) * Dh + d4 * 4);
        }
        __syncthreads();

        // S = Q K^T : thread computes rows r0,r0+1 x cols cg*8..cg*8+7
        float s0[8], s1[8];
#pragma unroll
        for (int i = 0; i < 8; i++) { s0[i] = 0.f; s1[i] = 0.f; }
#pragma unroll
        for (int kk = 0; kk < 16; kk++) {
            float4 qa = *(const float4*)&Qs[r0][kk * 4];
            float4 qb = *(const float4*)&Qs[r0 + 1][kk * 4];
#pragma unroll
            for (int ci = 0; ci < 8; ci++) {
                float4 kv = *(const float4*)&Ks[cg * 8 + ci][kk * 4];
                s0[ci] += qa.x * kv.x + qa.y * kv.y + qa.z * kv.z + qa.w * kv.w;
                s1[ci] += qb.x * kv.x + qb.y * kv.y + qb.z * kv.z + qb.w * kv.w;
            }
        }

        // Row max across this thread then across the 4 lanes of each row
        float mx0 = s0[0], mx1 = s1[0];
#pragma unroll
        for (int ci = 1; ci < 8; ci++) { mx0 = fmaxf(mx0, s0[ci]); mx1 = fmaxf(mx1, s1[ci]); }
#pragma unroll
        for (int off = 1; off <= 2; off <<= 1) {
            mx0 = fmaxf(mx0, __shfl_xor_sync(0xffffffffu, mx0, off));
            mx1 = fmaxf(mx1, __shfl_xor_sync(0xffffffffu, mx1, off));
        }
        float mn0 = fmaxf(m0, mx0), mn1 = fmaxf(m1, mx1);
        float al0 = __expf(m0 - mn0), al1 = __expf(m1 - mn1);
        m0 = mn0; m1 = mn1;

        float ls0 = 0.f, ls1 = 0.f;
#pragma unroll
        for (int ci = 0; ci < 8; ci++) {
            float p0 = __expf(s0[ci] - mn0);
            float p1 = __expf(s1[ci] - mn1);
            Ps[r0][cg * 8 + ci]     = p0;
            Ps[r0 + 1][cg * 8 + ci] = p1;
            ls0 += p0; ls1 += p1;
        }
#pragma unroll
        for (int off = 1; off <= 2; off <<= 1) {
            ls0 += __shfl_xor_sync(0xffffffffu, ls0, off);
            ls1 += __shfl_xor_sync(0xffffffffu, ls1, off);
        }
        l0 = l0 * al0 + ls0;
        l1 = l1 * al1 + ls1;
#pragma unroll
        for (int i = 0; i < 16; i++) { acc0[i] *= al0; acc1[i] *= al1; }

        __syncwarp();   // Ps written by the 4 same-warp lanes of each row

        // O += P V : thread accumulates dims cg*16..cg*16+15 of rows r0,r0+1
#pragma unroll
        for (int j = 0; j < KT; j++) {
            float p0 = Ps[r0][j];
            float p1 = Ps[r0 + 1][j];
#pragma unroll
            for (int c4 = 0; c4 < 4; c4++) {
                float4 vv = *(const float4*)&Vs[j][cg * 16 + c4 * 4];
                acc0[c4 * 4 + 0] += p0 * vv.x;
                acc0[c4 * 4 + 1] += p0 * vv.y;
                acc0[c4 * 4 + 2] += p0 * vv.z;
                acc0[c4 * 4 + 3] += p0 * vv.w;
                acc1[c4 * 4 + 0] += p1 * vv.x;
                acc1[c4 * 4 + 1] += p1 * vv.y;
                acc1[c4 * 4 + 2] += p1 * vv.z;
                acc1[c4 * 4 + 3] += p1 * vv.w;
            }
        }
        __syncwarp();   // Ps reads done before next tile's writes
    }

    // Epilogue: y[b, q0+r, h*64 + d] = acc / l
    const int bb = bh >> 4;
    const int h  = bh & 15;
    const float inv0 = 1.f / l0, inv1 = 1.f / l1;
    float* y0 = g_y + (size_t)(bb * Nseq + q0 + r0) * Cdim + h * Dh + cg * 16;
    float* y1 = y0 + Cdim;
#pragma unroll
    for (int c4 = 0; c4 < 4; c4++) {
        *(float4*)&y0[c4 * 4] = make_float4(acc0[c4 * 4] * inv0, acc0[c4 * 4 + 1] * inv0,
                                            acc0[c4 * 4 + 2] * inv0, acc0[c4 * 4 + 3] * inv0);
        *(float4*)&y1[c4 * 4] = make_float4(acc1[c4 * 4] * inv1, acc1[c4 * 4 + 1] * inv1,
                                            acc1[c4 * 4 + 2] * inv1, acc1[c4 * 4 + 3] * inv1);
    }
}

// ---------------------------------------------------------------------------
extern "C" void kernel_launch(void* const* d_in, const int* in_sizes, int n_in,
                              void* d_out, int out_size)
{
    const float* x      = (const float*)d_in[0];   // [4,2048,1024]
    const float* w_attn = (const float*)d_in[1];   // [1024,3072]
    const float* w_proj = (const float*)d_in[2];   // [1024,1024]
    float* out = (float*)d_out;                    // [4,2048,1024]

    (void)in_sizes; (void)n_in; (void)out_size;

    // 1) QKV projection, scattered into per-head [b,h,n,d] layouts
    sgemm_kernel<0><<<dim3((3 * Cdim) / 128, (Bz * Nseq) / 128), 256>>>(
        x, w_attn, nullptr, Bz * Nseq, 3 * Cdim, Cdim);

    // 2) Flash attention -> g_y [b,n,c]
    attn_kernel<<<dim3(Nseq / 64, BHn), 128>>>();

    // 3) Output projection -> d_out
    sgemm_kernel<1><<<dim3(Cdim / 128, (Bz * Nseq) / 128), 256>>>(
        nullptr, w_proj, out, Bz * Nseq, Cdim, Cdim);
}

// round 6
// speedup vs baseline: 1.1338x; 1.1338x over previous
#include <cuda_runtime.h>
#include <cuda_bf16.h>
#include <cstdint>
#include <cstring>

// Problem constants
#define Bz   4
#define Nseq 2048
#define Cdim 1024
#define Hn   16
#define Dh   64
#define BHn  (Bz * Hn)

// Scratch (device globals — no runtime allocation allowed).
// NOTE: these are referenced ONLY inside device code. Passing a __device__
// symbol as a host-side kernel argument passes the host shadow address
// (garbage on device) — that was the R3/R4 bug.
__device__ float g_q[(size_t)BHn * Nseq * Dh];   // [b,h,n,d]
__device__ float g_k[(size_t)BHn * Nseq * Dh];
__device__ float g_v[(size_t)BHn * Nseq * Dh];
__device__ float g_y[(size_t)Bz * Nseq * Cdim];  // [b,n,c]
// Pre-transposed + bf16-split weights: [F][K=1024] layout, K contiguous
__device__ __nv_bfloat16 g_w1t_hi[(size_t)3 * Cdim * Cdim];
__device__ __nv_bfloat16 g_w1t_lo[(size_t)3 * Cdim * Cdim];
__device__ __nv_bfloat16 g_w2t_hi[(size_t)Cdim * Cdim];
__device__ __nv_bfloat16 g_w2t_lo[(size_t)Cdim * Cdim];

// ---------------------------------------------------------------------------
// Warp-MMA helpers (base PTX — no sm_103a-only features)
// ---------------------------------------------------------------------------
__device__ __forceinline__ uint32_t smem_u32(const void* p) {
    uint32_t a;
    asm("{ .reg .u64 t; cvta.to.shared.u64 t, %1; cvt.u32.u64 %0, t; }" : "=r"(a) : "l"(p));
    return a;
}
__device__ __forceinline__ void ldsm4(uint32_t* r, uint32_t addr) {
    asm volatile("ldmatrix.sync.aligned.m8n8.x4.shared.b16 {%0,%1,%2,%3}, [%4];"
                 : "=r"(r[0]), "=r"(r[1]), "=r"(r[2]), "=r"(r[3]) : "r"(addr));
}
__device__ __forceinline__ void mma16816(float* c, const uint32_t* a, const uint32_t* b) {
    asm volatile(
        "mma.sync.aligned.m16n8k16.row.col.f32.bf16.bf16.f32 "
        "{%0,%1,%2,%3}, {%4,%5,%6,%7}, {%8,%9}, {%0,%1,%2,%3};"
        : "+f"(c[0]), "+f"(c[1]), "+f"(c[2]), "+f"(c[3])
        : "r"(a[0]), "r"(a[1]), "r"(a[2]), "r"(a[3]), "r"(b[0]), "r"(b[1]));
}
__device__ __forceinline__ uint32_t pack2(float a, float b) {
    __nv_bfloat162 t;
    t.x = __float2bfloat16_rn(a); t.y = __float2bfloat16_rn(b);
    uint32_t u; memcpy(&u, &t, 4); return u;
}

// ---------------------------------------------------------------------------
// Weight pre-pass: w [K=1024, F] fp32 -> hi/lo [F, 1024] bf16 (split transpose)
// W = 0: g_w1t_* (F=3072) ; W = 1: g_w2t_* (F=1024). Globals resolved in
// device code.
// ---------------------------------------------------------------------------
template <int W>
__global__ __launch_bounds__(256)
void split_transpose(const float* __restrict__ w, int F)
{
    __nv_bfloat16* hi = (W == 0) ? g_w1t_hi : g_w2t_hi;
    __nv_bfloat16* lo = (W == 0) ? g_w1t_lo : g_w2t_lo;
    __shared__ float t[32][33];
    const int f0 = blockIdx.x * 32, k0 = blockIdx.y * 32;
    const int x = threadIdx.x, y0 = threadIdx.y;
#pragma unroll
    for (int r = 0; r < 4; r++) {
        int ky = y0 + r * 8;
        t[ky][x] = w[(size_t)(k0 + ky) * F + f0 + x];
    }
    __syncthreads();
#pragma unroll
    for (int r = 0; r < 4; r++) {
        int fy = y0 + r * 8;
        float v = t[x][fy];
        __nv_bfloat16 h = __float2bfloat16_rn(v);
        __nv_bfloat16 l = __float2bfloat16_rn(v - __bfloat162float(h));
        size_t o = (size_t)(f0 + fy) * 1024 + k0 + x;
        hi[o] = h; lo[o] = l;
    }
}

// ---------------------------------------------------------------------------
// mma.sync GEMM: D[M,F] = A[M,1024] @ B^T  (B pre-transposed, [F][1024])
// bf16 3-term split, fp32 accum. Block tile 128x128, BK=32, 256 thr (8 warps,
// 2x4, warp tile 64x32). Single-buffered static smem + register prefetch.
// MODE 0: A = x param, B = g_w1t, scatter into g_q/g_k/g_v.
// MODE 1: A = g_y,     B = g_w2t, row-major Cout.
// ---------------------------------------------------------------------------
#define BK     32
#define ASTR   40                    // b16 row stride (80B): conflict-free ldmatrix
#define TILE_B (128 * ASTR * 2)      // bytes per array (10240)
#define OFF_AH 0
#define OFF_AL (1 * TILE_B)
#define OFF_BH (2 * TILE_B)
#define OFF_BL (3 * TILE_B)
#define SMEM_BYTES (4 * TILE_B)      // 40960
#define NKC    (1024 / BK)           // 32 k-chunks

template <int MODE>
__global__ __launch_bounds__(256)
void mma_gemm(const float* __restrict__ Ain, float* __restrict__ Cout)
{
    __shared__ __align__(128) char smem[SMEM_BYTES];
    const uint32_t sbase = smem_u32(smem);
    const int tid  = threadIdx.x;
    const int wid  = tid >> 5, lane = tid & 31;
    const int wm   = wid >> 2;           // 0..1 (m)
    const int wn   = wid & 3;            // 0..3 (n)
    const int bM   = blockIdx.y * 128, bN = blockIdx.x * 128;

    // Device-side resolution of globals (host must never pass these).
    const float*         A   = (MODE == 1) ? g_y : Ain;
    const __nv_bfloat16* Bhi = (MODE == 0) ? g_w1t_hi : g_w2t_hi;
    const __nv_bfloat16* Blo = (MODE == 0) ? g_w1t_lo : g_w2t_lo;

    const float*         Ap = A   + (size_t)bM * 1024;
    const __nv_bfloat16* Bh = Bhi + (size_t)bN * 1024;
    const __nv_bfloat16* Bl = Blo + (size_t)bN * 1024;

    float acc[4][4][4];
#pragma unroll
    for (int i = 0; i < 4; i++)
#pragma unroll
        for (int j = 0; j < 4; j++)
#pragma unroll
            for (int r = 0; r < 4; r++) acc[i][j][r] = 0.f;

    // ---- global->reg prefetch state ----
    float4 aReg[4];
    uint4  bhReg[2], blReg[2];

    auto gload = [&](int kt) {
        const int k0 = kt * BK;
#pragma unroll
        for (int i = 0; i < 4; i++) {
            int e = tid + i * 256;
            int r = e >> 3, c4 = e & 7;
            aReg[i] = *(const float4*)(Ap + (size_t)r * 1024 + k0 + c4 * 4);
        }
#pragma unroll
        for (int i = 0; i < 2; i++) {
            int e = tid + i * 256;
            int r = e >> 2, c8 = e & 3;
            bhReg[i] = *(const uint4*)(Bh + (size_t)r * 1024 + k0 + c8 * 8);
            blReg[i] = *(const uint4*)(Bl + (size_t)r * 1024 + k0 + c8 * 8);
        }
    };
    auto sstore = [&]() {
#pragma unroll
        for (int i = 0; i < 4; i++) {
            int e = tid + i * 256;
            int r = e >> 3, c4 = e & 7;
            float4 v = aReg[i];
            __nv_bfloat16 hx = __float2bfloat16_rn(v.x);
            __nv_bfloat16 hy = __float2bfloat16_rn(v.y);
            __nv_bfloat16 hz = __float2bfloat16_rn(v.z);
            __nv_bfloat16 hw = __float2bfloat16_rn(v.w);
            uint32_t off = (uint32_t)(r * ASTR + c4 * 4) * 2;
            __nv_bfloat162 h01; h01.x = hx; h01.y = hy;
            __nv_bfloat162 h23; h23.x = hz; h23.y = hw;
            uint2 hh; memcpy(&hh.x, &h01, 4); memcpy(&hh.y, &h23, 4);
            *(uint2*)(smem + OFF_AH + off) = hh;
            uint2 ll;
            ll.x = pack2(v.x - __bfloat162float(hx), v.y - __bfloat162float(hy));
            ll.y = pack2(v.z - __bfloat162float(hz), v.w - __bfloat162float(hw));
            *(uint2*)(smem + OFF_AL + off) = ll;
        }
#pragma unroll
        for (int i = 0; i < 2; i++) {
            int e = tid + i * 256;
            int r = e >> 2, c8 = e & 3;
            uint32_t off = (uint32_t)(r * ASTR + c8 * 8) * 2;
            *(uint4*)(smem + OFF_BH + off) = bhReg[i];
            *(uint4*)(smem + OFF_BL + off) = blReg[i];
        }
    };

    // frag address components (b16 units before *2)
    const uint32_t aRow = wm * 64 + (lane & 15);
    const uint32_t aCol = (uint32_t)(lane >> 4) << 3;
    const uint32_t bRow = wn * 32 + (((uint32_t)(lane >> 4)) << 3) + (lane & 7);
    const uint32_t bCol = (((uint32_t)(lane >> 3)) & 1) << 3;

    auto compute = [&]() {
#pragma unroll
        for (int ks = 0; ks < BK; ks += 16) {
            uint32_t ah[4][4], al[4][4], bh[4][2], bl[4][2];
#pragma unroll
            for (int mt = 0; mt < 4; mt++) {
                uint32_t off = ((aRow + mt * 16) * ASTR + ks + aCol) * 2;
                ldsm4(ah[mt], sbase + OFF_AH + off);
                ldsm4(al[mt], sbase + OFF_AL + off);
            }
#pragma unroll
            for (int g = 0; g < 2; g++) {
                uint32_t off = ((bRow + g * 16) * ASTR + ks + bCol) * 2;
                uint32_t t[4];
                ldsm4(t, sbase + OFF_BH + off);
                bh[g * 2][0] = t[0]; bh[g * 2][1] = t[1];
                bh[g * 2 + 1][0] = t[2]; bh[g * 2 + 1][1] = t[3];
                ldsm4(t, sbase + OFF_BL + off);
                bl[g * 2][0] = t[0]; bl[g * 2][1] = t[1];
                bl[g * 2 + 1][0] = t[2]; bl[g * 2 + 1][1] = t[3];
            }
#pragma unroll
            for (int mt = 0; mt < 4; mt++)
#pragma unroll
                for (int nt = 0; nt < 4; nt++) {
                    mma16816(acc[mt][nt], ah[mt], bh[nt]);
                    mma16816(acc[mt][nt], ah[mt], bl[nt]);
                    mma16816(acc[mt][nt], al[mt], bh[nt]);
                }
        }
    };

    gload(0);
    sstore();
    __syncthreads();
    for (int kt = 0; kt < NKC; kt++) {
        if (kt + 1 < NKC) gload(kt + 1);   // prefetch next chunk into registers
        compute();                          // consume current smem contents
        __syncthreads();                    // everyone done reading
        if (kt + 1 < NKC) sstore();         // overwrite single buffer
        __syncthreads();                    // writes visible
    }

    // Epilogue. acc frag: c0,c1 @ (row=lane>>2, col=(lane&3)*2); c2,c3 @ row+8
    const int rq = lane >> 2, cq = (lane & 3) * 2;
#pragma unroll
    for (int mt = 0; mt < 4; mt++) {
        int m0 = bM + wm * 64 + mt * 16 + rq;
#pragma unroll
        for (int nt = 0; nt < 4; nt++) {
            int f = bN + wn * 32 + nt * 8 + cq;
            if (MODE == 0) {
                int sec = f >> 10, cc = f & (Cdim - 1);
                int h = cc >> 6, d = cc & 63;
                float* dst = (sec == 0) ? g_q : (sec == 1) ? g_k : g_v;
#pragma unroll
                for (int half = 0; half < 2; half++) {
                    int m = m0 + half * 8;
                    float* p = dst + (((size_t)(m >> 11) * Hn + h) * Nseq + (m & (Nseq - 1))) * Dh + d;
                    *(float2*)p = make_float2(acc[mt][nt][half * 2], acc[mt][nt][half * 2 + 1]);
                }
            } else {
#pragma unroll
                for (int half = 0; half < 2; half++) {
                    int m = m0 + half * 8;
                    float* p = Cout + (size_t)m * Cdim + f;
                    *(float2*)p = make_float2(acc[mt][nt][half * 2], acc[mt][nt][half * 2 + 1]);
                }
            }
        }
    }
}

// ---------------------------------------------------------------------------
// Flash attention (fp32, unchanged from R1): one block per (b*H+h, 64-q tile)
// ---------------------------------------------------------------------------
#define KT 32

__global__ __launch_bounds__(128)
void attn_kernel()
{
    __shared__ float Qs[64][64];
    __shared__ float Ks[KT][64];
    __shared__ float Vs[KT][64];
    __shared__ float Ps[64][KT + 1];

    const int tid = threadIdx.x;
    const int bh  = blockIdx.y;
    const int q0  = blockIdx.x * 64;
    const int cg  = tid & 3;
    const int rp  = tid >> 2;
    const int r0  = rp * 2;

    const float* Qg = g_q + (size_t)bh * Nseq * Dh;
    const float* Kg = g_k + (size_t)bh * Nseq * Dh;
    const float* Vg = g_v + (size_t)bh * Nseq * Dh;

#pragma unroll
    for (int i = 0; i < 8; i++) {
        int e = tid + i * 128;
        int r = e >> 4, d4 = e & 15;
        float4 v = *(const float4*)(Qg + (size_t)(q0 + r) * Dh + d4 * 4);
        v.x *= 0.125f; v.y *= 0.125f; v.z *= 0.125f; v.w *= 0.125f;
        *(float4*)&Qs[r][d4 * 4] = v;
    }

    float m0 = -1e30f, m1 = -1e30f;
    float l0 = 0.f,    l1 = 0.f;
    float acc0[16], acc1[16];
#pragma unroll
    for (int i = 0; i < 16; i++) { acc0[i] = 0.f; acc1[i] = 0.f; }

    for (int j0 = 0; j0 < Nseq; j0 += KT) {
        __syncthreads();
#pragma unroll
        for (int i = 0; i < (KT * 16) / 128; i++) {
            int e = tid + i * 128;
            int r = e >> 4, d4 = e & 15;
            *(float4*)&Ks[r][d4 * 4] = *(const float4*)(Kg + (size_t)(j0 + r) * Dh + d4 * 4);
            *(float4*)&Vs[r][d4 * 4] = *(const float4*)(Vg + (size_t)(j0 + r) * Dh + d4 * 4);
        }
        __syncthreads();

        float s0[8], s1[8];
#pragma unroll
        for (int i = 0; i < 8; i++) { s0[i] = 0.f; s1[i] = 0.f; }
#pragma unroll
        for (int kk = 0; kk < 16; kk++) {
            float4 qa = *(const float4*)&Qs[r0][kk * 4];
            float4 qb = *(const float4*)&Qs[r0 + 1][kk * 4];
#pragma unroll
            for (int ci = 0; ci < 8; ci++) {
                float4 kv = *(const float4*)&Ks[cg * 8 + ci][kk * 4];
                s0[ci] += qa.x * kv.x + qa.y * kv.y + qa.z * kv.z + qa.w * kv.w;
                s1[ci] += qb.x * kv.x + qb.y * kv.y + qb.z * kv.z + qb.w * kv.w;
            }
        }

        float mx0 = s0[0], mx1 = s1[0];
#pragma unroll
        for (int ci = 1; ci < 8; ci++) { mx0 = fmaxf(mx0, s0[ci]); mx1 = fmaxf(mx1, s1[ci]); }
#pragma unroll
        for (int off = 1; off <= 2; off <<= 1) {
            mx0 = fmaxf(mx0, __shfl_xor_sync(0xffffffffu, mx0, off));
            mx1 = fmaxf(mx1, __shfl_xor_sync(0xffffffffu, mx1, off));
        }
        float mn0 = fmaxf(m0, mx0), mn1 = fmaxf(m1, mx1);
        float al0 = __expf(m0 - mn0), al1 = __expf(m1 - mn1);
        m0 = mn0; m1 = mn1;

        float ls0 = 0.f, ls1 = 0.f;
#pragma unroll
        for (int ci = 0; ci < 8; ci++) {
            float p0 = __expf(s0[ci] - mn0);
            float p1 = __expf(s1[ci] - mn1);
            Ps[r0][cg * 8 + ci]     = p0;
            Ps[r0 + 1][cg * 8 + ci] = p1;
            ls0 += p0; ls1 += p1;
        }
#pragma unroll
        for (int off = 1; off <= 2; off <<= 1) {
            ls0 += __shfl_xor_sync(0xffffffffu, ls0, off);
            ls1 += __shfl_xor_sync(0xffffffffu, ls1, off);
        }
        l0 = l0 * al0 + ls0;
        l1 = l1 * al1 + ls1;
#pragma unroll
        for (int i = 0; i < 16; i++) { acc0[i] *= al0; acc1[i] *= al1; }

        __syncwarp();

#pragma unroll
        for (int j = 0; j < KT; j++) {
            float p0 = Ps[r0][j];
            float p1 = Ps[r0 + 1][j];
#pragma unroll
            for (int c4 = 0; c4 < 4; c4++) {
                float4 vv = *(const float4*)&Vs[j][cg * 16 + c4 * 4];
                acc0[c4 * 4 + 0] += p0 * vv.x;
                acc0[c4 * 4 + 1] += p0 * vv.y;
                acc0[c4 * 4 + 2] += p0 * vv.z;
                acc0[c4 * 4 + 3] += p0 * vv.w;
                acc1[c4 * 4 + 0] += p1 * vv.x;
                acc1[c4 * 4 + 1] += p1 * vv.y;
                acc1[c4 * 4 + 2] += p1 * vv.z;
                acc1[c4 * 4 + 3] += p1 * vv.w;
            }
        }
        __syncwarp();
    }

    const int bb = bh >> 4;
    const int h  = bh & 15;
    const float inv0 = 1.f / l0, inv1 = 1.f / l1;
    float* y0 = g_y + (size_t)(bb * Nseq + q0 + r0) * Cdim + h * Dh + cg * 16;
    float* y1 = y0 + Cdim;
#pragma unroll
    for (int c4 = 0; c4 < 4; c4++) {
        *(float4*)&y0[c4 * 4] = make_float4(acc0[c4 * 4] * inv0, acc0[c4 * 4 + 1] * inv0,
                                            acc0[c4 * 4 + 2] * inv0, acc0[c4 * 4 + 3] * inv0);
        *(float4*)&y1[c4 * 4] = make_float4(acc1[c4 * 4] * inv1, acc1[c4 * 4 + 1] * inv1,
                                            acc1[c4 * 4 + 2] * inv1, acc1[c4 * 4 + 3] * inv1);
    }
}

// ---------------------------------------------------------------------------
extern "C" void kernel_launch(void* const* d_in, const int* in_sizes, int n_in,
                              void* d_out, int out_size)
{
    const float* x      = (const float*)d_in[0];   // [4,2048,1024]
    const float* w_attn = (const float*)d_in[1];   // [1024,3072]
    const float* w_proj = (const float*)d_in[2];   // [1024,1024]
    float* out = (float*)d_out;                    // [4,2048,1024]
    (void)in_sizes; (void)n_in; (void)out_size;

    // 0) Weight pre-pass: transpose + bf16 hi/lo split (globals resolved on device)
    split_transpose<0><<<dim3(3 * Cdim / 32, Cdim / 32), dim3(32, 8)>>>(w_attn, 3 * Cdim);
    split_transpose<1><<<dim3(Cdim / 32, Cdim / 32), dim3(32, 8)>>>(w_proj, Cdim);

    // 1) QKV projection (mma.sync), scattered into per-head [b,h,n,d]
    mma_gemm<0><<<dim3(3 * Cdim / 128, (Bz * Nseq) / 128), 256>>>(x, nullptr);

    // 2) Flash attention -> g_y [b,n,c]
    attn_kernel<<<dim3(Nseq / 64, BHn), 128>>>();

    // 3) Output projection (mma.sync) -> d_out
    mma_gemm<1><<<dim3(Cdim / 128, (Bz * Nseq) / 128), 256>>>(nullptr, out);
}

// round 8
// speedup vs baseline: 5.8244x; 5.1370x over previous
#include <cuda_runtime.h>
#include <cuda_bf16.h>
#include <cstdint>
#include <cstring>

// Problem constants
#define Bz   4
#define Nseq 2048
#define Cdim 1024
#define Hn   16
#define Dh   64
#define BHn  (Bz * Hn)

// Scratch (device globals; referenced ONLY inside device code — host passing
// of __device__ symbols was the R3/R4 bug).
__device__ float g_y[(size_t)Bz * Nseq * Cdim];  // [b,n,c]
// q/k/v as bf16 hi/lo splits, [bh][n][d]; q pre-scaled by 0.125
__device__ __nv_bfloat16 g_qh[(size_t)BHn * Nseq * Dh];
__device__ __nv_bfloat16 g_ql[(size_t)BHn * Nseq * Dh];
__device__ __nv_bfloat16 g_kh[(size_t)BHn * Nseq * Dh];
__device__ __nv_bfloat16 g_kl[(size_t)BHn * Nseq * Dh];
__device__ __nv_bfloat16 g_vh[(size_t)BHn * Nseq * Dh];
__device__ __nv_bfloat16 g_vl[(size_t)BHn * Nseq * Dh];
// Pre-transposed + bf16-split weights: [F][K=1024] layout, K contiguous
__device__ __nv_bfloat16 g_w1t_hi[(size_t)3 * Cdim * Cdim];
__device__ __nv_bfloat16 g_w1t_lo[(size_t)3 * Cdim * Cdim];
__device__ __nv_bfloat16 g_w2t_hi[(size_t)Cdim * Cdim];
__device__ __nv_bfloat16 g_w2t_lo[(size_t)Cdim * Cdim];

// ---------------------------------------------------------------------------
// Warp-MMA helpers (base PTX — no sm_103a-only features)
// ---------------------------------------------------------------------------
__device__ __forceinline__ uint32_t smem_u32(const void* p) {
    uint32_t a;
    asm("{ .reg .u64 t; cvta.to.shared.u64 t, %1; cvt.u32.u64 %0, t; }" : "=r"(a) : "l"(p));
    return a;
}
__device__ __forceinline__ void ldsm4(uint32_t* r, uint32_t addr) {
    asm volatile("ldmatrix.sync.aligned.m8n8.x4.shared.b16 {%0,%1,%2,%3}, [%4];"
                 : "=r"(r[0]), "=r"(r[1]), "=r"(r[2]), "=r"(r[3]) : "r"(addr));
}
__device__ __forceinline__ void ldsm4t(uint32_t* r, uint32_t addr) {
    asm volatile("ldmatrix.sync.aligned.m8n8.x4.trans.shared.b16 {%0,%1,%2,%3}, [%4];"
                 : "=r"(r[0]), "=r"(r[1]), "=r"(r[2]), "=r"(r[3]) : "r"(addr));
}
__device__ __forceinline__ void mma16816(float* c, const uint32_t* a, const uint32_t* b) {
    asm volatile(
        "mma.sync.aligned.m16n8k16.row.col.f32.bf16.bf16.f32 "
        "{%0,%1,%2,%3}, {%4,%5,%6,%7}, {%8,%9}, {%0,%1,%2,%3};"
        : "+f"(c[0]), "+f"(c[1]), "+f"(c[2]), "+f"(c[3])
        : "r"(a[0]), "r"(a[1]), "r"(a[2]), "r"(a[3]), "r"(b[0]), "r"(b[1]));
}
__device__ __forceinline__ void cpa16(uint32_t daddr, const void* g) {
    asm volatile("cp.async.cg.shared.global [%0], [%1], 16;" :: "r"(daddr), "l"(g));
}
__device__ __forceinline__ void cpa_commit() { asm volatile("cp.async.commit_group;"); }
template <int N> __device__ __forceinline__ void cpa_wait() {
    asm volatile("cp.async.wait_group %0;" :: "n"(N));
}
__device__ __forceinline__ uint32_t pack2(float a, float b) {
    __nv_bfloat162 t;
    t.x = __float2bfloat16_rn(a); t.y = __float2bfloat16_rn(b);
    uint32_t u; memcpy(&u, &t, 4); return u;
}

// ---------------------------------------------------------------------------
// Weight pre-pass: w [K=1024, F] fp32 -> hi/lo [F, 1024] bf16 (split transpose)
// ---------------------------------------------------------------------------
template <int W>
__global__ __launch_bounds__(256)
void split_transpose(const float* __restrict__ w, int F)
{
    __nv_bfloat16* hi = (W == 0) ? g_w1t_hi : g_w2t_hi;
    __nv_bfloat16* lo = (W == 0) ? g_w1t_lo : g_w2t_lo;
    __shared__ float t[32][33];
    const int f0 = blockIdx.x * 32, k0 = blockIdx.y * 32;
    const int x = threadIdx.x, y0 = threadIdx.y;
#pragma unroll
    for (int r = 0; r < 4; r++) {
        int ky = y0 + r * 8;
        t[ky][x] = w[(size_t)(k0 + ky) * F + f0 + x];
    }
    __syncthreads();
#pragma unroll
    for (int r = 0; r < 4; r++) {
        int fy = y0 + r * 8;
        float v = t[x][fy];
        __nv_bfloat16 h = __float2bfloat16_rn(v);
        __nv_bfloat16 l = __float2bfloat16_rn(v - __bfloat162float(h));
        size_t o = (size_t)(f0 + fy) * 1024 + k0 + x;
        hi[o] = h; lo[o] = l;
    }
}

// ---------------------------------------------------------------------------
// mma.sync GEMM (structure verified in R6). MODE 0: epilogue splits q/k/v to
// bf16 hi/lo globals (q scaled 0.125). MODE 1: A = g_y, row-major fp32 out.
// ---------------------------------------------------------------------------
#define BK     32
#define ASTR   40
#define TILE_B (128 * ASTR * 2)
#define OFF_AH 0
#define OFF_AL (1 * TILE_B)
#define OFF_BH (2 * TILE_B)
#define OFF_BL (3 * TILE_B)
#define SMEM_BYTES (4 * TILE_B)
#define NKC    (1024 / BK)

template <int MODE>
__global__ __launch_bounds__(256)
void mma_gemm(const float* __restrict__ Ain, float* __restrict__ Cout)
{
    __shared__ __align__(128) char smem[SMEM_BYTES];
    const uint32_t sbase = smem_u32(smem);
    const int tid  = threadIdx.x;
    const int wid  = tid >> 5, lane = tid & 31;
    const int wm   = wid >> 2;
    const int wn   = wid & 3;
    const int bM   = blockIdx.y * 128, bN = blockIdx.x * 128;

    const float*         A   = (MODE == 1) ? g_y : Ain;
    const __nv_bfloat16* Bhi = (MODE == 0) ? g_w1t_hi : g_w2t_hi;
    const __nv_bfloat16* Blo = (MODE == 0) ? g_w1t_lo : g_w2t_lo;

    const float*         Ap = A   + (size_t)bM * 1024;
    const __nv_bfloat16* Bh = Bhi + (size_t)bN * 1024;
    const __nv_bfloat16* Bl = Blo + (size_t)bN * 1024;

    float acc[4][4][4];
#pragma unroll
    for (int i = 0; i < 4; i++)
#pragma unroll
        for (int j = 0; j < 4; j++)
#pragma unroll
            for (int r = 0; r < 4; r++) acc[i][j][r] = 0.f;

    float4 aReg[4];
    uint4  bhReg[2], blReg[2];

    auto gload = [&](int kt) {
        const int k0 = kt * BK;
#pragma unroll
        for (int i = 0; i < 4; i++) {
            int e = tid + i * 256;
            int r = e >> 3, c4 = e & 7;
            aReg[i] = *(const float4*)(Ap + (size_t)r * 1024 + k0 + c4 * 4);
        }
#pragma unroll
        for (int i = 0; i < 2; i++) {
            int e = tid + i * 256;
            int r = e >> 2, c8 = e & 3;
            bhReg[i] = *(const uint4*)(Bh + (size_t)r * 1024 + k0 + c8 * 8);
            blReg[i] = *(const uint4*)(Bl + (size_t)r * 1024 + k0 + c8 * 8);
        }
    };
    auto sstore = [&]() {
#pragma unroll
        for (int i = 0; i < 4; i++) {
            int e = tid + i * 256;
            int r = e >> 3, c4 = e & 7;
            float4 v = aReg[i];
            __nv_bfloat16 hx = __float2bfloat16_rn(v.x);
            __nv_bfloat16 hy = __float2bfloat16_rn(v.y);
            __nv_bfloat16 hz = __float2bfloat16_rn(v.z);
            __nv_bfloat16 hw = __float2bfloat16_rn(v.w);
            uint32_t off = (uint32_t)(r * ASTR + c4 * 4) * 2;
            __nv_bfloat162 h01; h01.x = hx; h01.y = hy;
            __nv_bfloat162 h23; h23.x = hz; h23.y = hw;
            uint2 hh; memcpy(&hh.x, &h01, 4); memcpy(&hh.y, &h23, 4);
            *(uint2*)(smem + OFF_AH + off) = hh;
            uint2 ll;
            ll.x = pack2(v.x - __bfloat162float(hx), v.y - __bfloat162float(hy));
            ll.y = pack2(v.z - __bfloat162float(hz), v.w - __bfloat162float(hw));
            *(uint2*)(smem + OFF_AL + off) = ll;
        }
#pragma unroll
        for (int i = 0; i < 2; i++) {
            int e = tid + i * 256;
            int r = e >> 2, c8 = e & 3;
            uint32_t off = (uint32_t)(r * ASTR + c8 * 8) * 2;
            *(uint4*)(smem + OFF_BH + off) = bhReg[i];
            *(uint4*)(smem + OFF_BL + off) = blReg[i];
        }
    };

    const uint32_t aRow = wm * 64 + (lane & 15);
    const uint32_t aCol = (uint32_t)(lane >> 4) << 3;
    const uint32_t bRow = wn * 32 + (((uint32_t)(lane >> 4)) << 3) + (lane & 7);
    const uint32_t bCol = (((uint32_t)(lane >> 3)) & 1) << 3;

    auto compute = [&]() {
#pragma unroll
        for (int ks = 0; ks < BK; ks += 16) {
            uint32_t ah[4][4], al[4][4], bh[4][2], bl[4][2];
#pragma unroll
            for (int mt = 0; mt < 4; mt++) {
                uint32_t off = ((aRow + mt * 16) * ASTR + ks + aCol) * 2;
                ldsm4(ah[mt], sbase + OFF_AH + off);
                ldsm4(al[mt], sbase + OFF_AL + off);
            }
#pragma unroll
            for (int g = 0; g < 2; g++) {
                uint32_t off = ((bRow + g * 16) * ASTR + ks + bCol) * 2;
                uint32_t t[4];
                ldsm4(t, sbase + OFF_BH + off);
                bh[g * 2][0] = t[0]; bh[g * 2][1] = t[1];
                bh[g * 2 + 1][0] = t[2]; bh[g * 2 + 1][1] = t[3];
                ldsm4(t, sbase + OFF_BL + off);
                bl[g * 2][0] = t[0]; bl[g * 2][1] = t[1];
                bl[g * 2 + 1][0] = t[2]; bl[g * 2 + 1][1] = t[3];
            }
#pragma unroll
            for (int mt = 0; mt < 4; mt++)
#pragma unroll
                for (int nt = 0; nt < 4; nt++) {
                    mma16816(acc[mt][nt], ah[mt], bh[nt]);
                    mma16816(acc[mt][nt], ah[mt], bl[nt]);
                    mma16816(acc[mt][nt], al[mt], bh[nt]);
                }
        }
    };

    gload(0);
    sstore();
    __syncthreads();
    for (int kt = 0; kt < NKC; kt++) {
        if (kt + 1 < NKC) gload(kt + 1);
        compute();
        __syncthreads();
        if (kt + 1 < NKC) sstore();
        __syncthreads();
    }

    const int rq = lane >> 2, cq = (lane & 3) * 2;
#pragma unroll
    for (int mt = 0; mt < 4; mt++) {
        int m0 = bM + wm * 64 + mt * 16 + rq;
#pragma unroll
        for (int nt = 0; nt < 4; nt++) {
            int f = bN + wn * 32 + nt * 8 + cq;
            if (MODE == 0) {
                int sec = f >> 10, cc = f & (Cdim - 1);
                int h = cc >> 6, d = cc & 63;
                __nv_bfloat16* dhp = (sec == 0) ? g_qh : (sec == 1) ? g_kh : g_vh;
                __nv_bfloat16* dlp = (sec == 0) ? g_ql : (sec == 1) ? g_kl : g_vl;
                float scale = (sec == 0) ? 0.125f : 1.0f;
#pragma unroll
                for (int half = 0; half < 2; half++) {
                    int m = m0 + half * 8;
                    float v0 = acc[mt][nt][half * 2] * scale;
                    float v1 = acc[mt][nt][half * 2 + 1] * scale;
                    __nv_bfloat16 h0 = __float2bfloat16_rn(v0);
                    __nv_bfloat16 h1 = __float2bfloat16_rn(v1);
                    size_t idx = (((size_t)(m >> 11) * Hn + h) * Nseq + (m & (Nseq - 1))) * Dh + d;
                    __nv_bfloat162 hp; hp.x = h0; hp.y = h1;
                    uint32_t hw; memcpy(&hw, &hp, 4);
                    *(uint32_t*)&dhp[idx] = hw;
                    *(uint32_t*)&dlp[idx] = pack2(v0 - __bfloat162float(h0),
                                                  v1 - __bfloat162float(h1));
                }
            } else {
#pragma unroll
                for (int half = 0; half < 2; half++) {
                    int m = m0 + half * 8;
                    float* p = Cout + (size_t)m * Cdim + f;
                    *(float2*)p = make_float2(acc[mt][nt][half * 2], acc[mt][nt][half * 2 + 1]);
                }
            }
        }
    }
}

// ---------------------------------------------------------------------------
// Flash attention via mma.sync. Block: one (b,h) x 64 q-rows, 128 thr (4 warps,
// warp = 16 rows). KT=32 keys/tile, cp.async double-buffered K/V (hi/lo).
// QK^T and PV both 3-term split-bf16, fp32 softmax, fp32 accum.
// ---------------------------------------------------------------------------
#define AKT   32
#define ANT   (Nseq / AKT)            // 64 tiles
#define DSTR  72                      // b16 row stride (144B), conflict-free ldsm
#define ATILE (AKT * DSTR * 2)        // 4608 B
#define ABUF  (4 * ATILE)             // 18432 B (Kh,Kl,Vh,Vl)

__global__ __launch_bounds__(128)
void attn_mma()
{
    __shared__ __align__(128) char smem[2 * ABUF];  // 36864 B (static)
    const uint32_t sbase = smem_u32(smem);
    const int tid = threadIdx.x, lane = tid & 31, wid = tid >> 5;
    const int bh = blockIdx.y, q0 = blockIdx.x * 64;

    const __nv_bfloat16* Qhp = g_qh + ((size_t)bh * Nseq + q0) * Dh;
    const __nv_bfloat16* Qlp = g_ql + ((size_t)bh * Nseq + q0) * Dh;
    const __nv_bfloat16* Khp = g_kh + (size_t)bh * Nseq * Dh;
    const __nv_bfloat16* Klp = g_kl + (size_t)bh * Nseq * Dh;
    const __nv_bfloat16* Vhp = g_vh + (size_t)bh * Nseq * Dh;
    const __nv_bfloat16* Vlp = g_vl + (size_t)bh * Nseq * Dh;

    // ---- stage Q (64x64 hi/lo) into the two buffers, then frag to registers
#pragma unroll
    for (int i = 0; i < 4; i++) {
        int e = tid + i * 128;            // 512 x 16B per array
        int r = e >> 3, c8 = e & 7;
        *(uint4*)(smem + r * (DSTR * 2) + c8 * 16) =
            *(const uint4*)(Qhp + (size_t)r * Dh + c8 * 8);
        *(uint4*)(smem + ABUF + r * (DSTR * 2) + c8 * 16) =
            *(const uint4*)(Qlp + (size_t)r * Dh + c8 * 8);
    }
    __syncthreads();

    uint32_t qh[4][4], ql[4][4];
    {
        uint32_t row = wid * 16 + (lane & 15);
        uint32_t col = ((uint32_t)(lane >> 4) & 1) << 3;
#pragma unroll
        for (int kc = 0; kc < 4; kc++) {
            uint32_t off = (row * DSTR + kc * 16 + col) * 2;
            ldsm4(qh[kc], sbase + off);
            ldsm4(ql[kc], sbase + ABUF + off);
        }
    }
    __syncthreads();   // staged Q consumed; buffers free for K/V

    float m0 = -1e30f, m1 = -1e30f, l0 = 0.f, l1 = 0.f;
    float y[8][4];
#pragma unroll
    for (int i = 0; i < 8; i++)
#pragma unroll
        for (int j = 0; j < 4; j++) y[i][j] = 0.f;

    auto issue = [&](int t, int b) {
        uint32_t dbase = sbase + b * ABUF;
        const __nv_bfloat16* kh = Khp + (size_t)t * AKT * Dh;
        const __nv_bfloat16* kl = Klp + (size_t)t * AKT * Dh;
        const __nv_bfloat16* vh = Vhp + (size_t)t * AKT * Dh;
        const __nv_bfloat16* vl = Vlp + (size_t)t * AKT * Dh;
#pragma unroll
        for (int i = 0; i < 2; i++) {
            int e = tid + i * 128;        // 256 x 16B per array
            int r = e >> 3, c8 = e & 7;
            uint32_t doff = r * (DSTR * 2) + c8 * 16;
            size_t goff = (size_t)r * Dh + c8 * 8;
            cpa16(dbase + 0 * ATILE + doff, kh + goff);
            cpa16(dbase + 1 * ATILE + doff, kl + goff);
            cpa16(dbase + 2 * ATILE + doff, vh + goff);
            cpa16(dbase + 3 * ATILE + doff, vl + goff);
        }
        cpa_commit();
    };

    issue(0, 0);
    for (int t = 0; t < ANT; t++) {
        const int b = t & 1;
        if (t + 1 < ANT) { issue(t + 1, b ^ 1); cpa_wait<1>(); }
        else             { cpa_wait<0>(); }
        __syncthreads();

        const uint32_t kb = sbase + b * ABUF;

        // ---- S = Q K^T (4 n-tiles of 8 keys) ----
        float s[4][4];
#pragma unroll
        for (int i = 0; i < 4; i++)
#pragma unroll
            for (int j = 0; j < 4; j++) s[i][j] = 0.f;
        {
            uint32_t brow = (((uint32_t)(lane >> 4)) << 3) + (lane & 7);
            uint32_t bcol = (((uint32_t)(lane >> 3)) & 1) << 3;
#pragma unroll
            for (int kc = 0; kc < 4; kc++) {
                uint32_t kfh[8], kfl[8];
#pragma unroll
                for (int kg = 0; kg < 2; kg++) {
                    uint32_t off = ((brow + kg * 16) * DSTR + kc * 16 + bcol) * 2;
                    ldsm4(kfh + kg * 4, kb + 0 * ATILE + off);
                    ldsm4(kfl + kg * 4, kb + 1 * ATILE + off);
                }
#pragma unroll
                for (int nt = 0; nt < 4; nt++) {
                    uint32_t bhf[2] = {kfh[nt * 2], kfh[nt * 2 + 1]};
                    uint32_t blf[2] = {kfl[nt * 2], kfl[nt * 2 + 1]};
                    mma16816(s[nt], qh[kc], bhf);
                    mma16816(s[nt], qh[kc], blf);
                    mma16816(s[nt], ql[kc], bhf);
                }
            }
        }

        // ---- online softmax (rows r0 = lane>>2, r0+8) ----
        float mx0 = s[0][0], mx1 = s[0][2];
#pragma unroll
        for (int nt = 0; nt < 4; nt++) {
            mx0 = fmaxf(mx0, fmaxf(s[nt][0], s[nt][1]));
            mx1 = fmaxf(mx1, fmaxf(s[nt][2], s[nt][3]));
        }
#pragma unroll
        for (int off = 1; off <= 2; off <<= 1) {
            mx0 = fmaxf(mx0, __shfl_xor_sync(0xffffffffu, mx0, off));
            mx1 = fmaxf(mx1, __shfl_xor_sync(0xffffffffu, mx1, off));
        }
        float mn0 = fmaxf(m0, mx0), mn1 = fmaxf(m1, mx1);
        float al0 = __expf(m0 - mn0), al1 = __expf(m1 - mn1);
        m0 = mn0; m1 = mn1;

        float ls0 = 0.f, ls1 = 0.f;
#pragma unroll
        for (int nt = 0; nt < 4; nt++) {
            s[nt][0] = __expf(s[nt][0] - mn0);
            s[nt][1] = __expf(s[nt][1] - mn0);
            s[nt][2] = __expf(s[nt][2] - mn1);
            s[nt][3] = __expf(s[nt][3] - mn1);
            ls0 += s[nt][0] + s[nt][1];
            ls1 += s[nt][2] + s[nt][3];
        }
#pragma unroll
        for (int off = 1; off <= 2; off <<= 1) {
            ls0 += __shfl_xor_sync(0xffffffffu, ls0, off);
            ls1 += __shfl_xor_sync(0xffffffffu, ls1, off);
        }
        l0 = l0 * al0 + ls0;
        l1 = l1 * al1 + ls1;
#pragma unroll
        for (int dt = 0; dt < 8; dt++) {
            y[dt][0] *= al0; y[dt][1] *= al0;
            y[dt][2] *= al1; y[dt][3] *= al1;
        }

        // ---- P -> A-frags, hi/lo split ----
        uint32_t pah[2][4], pal[2][4];
#pragma unroll
        for (int kc = 0; kc < 2; kc++) {
#pragma unroll
            for (int q = 0; q < 4; q++) {
                // q=0: tile 2kc (c0,c1) ; q=1: tile 2kc (c2,c3)
                // q=2: tile 2kc+1 (c0,c1) ; q=3: tile 2kc+1 (c2,c3)
                int nt = 2 * kc + (q >> 1);
                int j0 = (q & 1) * 2;
                float p0 = s[nt][j0], p1 = s[nt][j0 + 1];
                __nv_bfloat16 h0 = __float2bfloat16_rn(p0);
                __nv_bfloat16 h1 = __float2bfloat16_rn(p1);
                __nv_bfloat162 hp; hp.x = h0; hp.y = h1;
                memcpy(&pah[kc][q], &hp, 4);
                pal[kc][q] = pack2(p0 - __bfloat162float(h0), p1 - __bfloat162float(h1));
            }
        }

        // ---- y += P V ----
        {
            uint32_t vrow = lane & 15;
            uint32_t vcol = ((uint32_t)(lane >> 4) & 1) << 3;
#pragma unroll
            for (int kc = 0; kc < 2; kc++) {
#pragma unroll
                for (int dg = 0; dg < 4; dg++) {
                    uint32_t off = ((kc * 16 + vrow) * DSTR + dg * 16 + vcol) * 2;
                    uint32_t vfh[4], vfl[4];
                    ldsm4t(vfh, kb + 2 * ATILE + off);
                    ldsm4t(vfl, kb + 3 * ATILE + off);
                    uint32_t b0h[2] = {vfh[0], vfh[1]}, b1h[2] = {vfh[2], vfh[3]};
                    uint32_t b0l[2] = {vfl[0], vfl[1]}, b1l[2] = {vfl[2], vfl[3]};
                    mma16816(y[dg * 2],     pah[kc], b0h);
                    mma16816(y[dg * 2],     pah[kc], b0l);
                    mma16816(y[dg * 2],     pal[kc], b0h);
                    mma16816(y[dg * 2 + 1], pah[kc], b1h);
                    mma16816(y[dg * 2 + 1], pah[kc], b1l);
                    mma16816(y[dg * 2 + 1], pal[kc], b1h);
                }
            }
        }
        __syncthreads();   // all warps done with buf b before it is refilled
    }

    // ---- epilogue: y /= l -> g_y[b, n, h*64+d] (fp32) ----
    const int bb = bh >> 4, hh = bh & 15;
    const float inv0 = 1.f / l0, inv1 = 1.f / l1;
    const int r0g = q0 + wid * 16 + (lane >> 2);
    float* yp0 = g_y + ((size_t)bb * Nseq + r0g) * Cdim + hh * Dh + (lane & 3) * 2;
    float* yp1 = yp0 + (size_t)8 * Cdim;
#pragma unroll
    for (int dt = 0; dt < 8; dt++) {
        *(float2*)(yp0 + dt * 8) = make_float2(y[dt][0] * inv0, y[dt][1] * inv0);
        *(float2*)(yp1 + dt * 8) = make_float2(y[dt][2] * inv1, y[dt][3] * inv1);
    }
}

// ---------------------------------------------------------------------------
extern "C" void kernel_launch(void* const* d_in, const int* in_sizes, int n_in,
                              void* d_out, int out_size)
{
    const float* x      = (const float*)d_in[0];   // [4,2048,1024]
    const float* w_attn = (const float*)d_in[1];   // [1024,3072]
    const float* w_proj = (const float*)d_in[2];   // [1024,1024]
    float* out = (float*)d_out;                    // [4,2048,1024]
    (void)in_sizes; (void)n_in; (void)out_size;

    // 0) Weight pre-pass
    split_transpose<0><<<dim3(3 * Cdim / 32, Cdim / 32), dim3(32, 8)>>>(w_attn, 3 * Cdim);
    split_transpose<1><<<dim3(Cdim / 32, Cdim / 32), dim3(32, 8)>>>(w_proj, Cdim);

    // 1) QKV projection -> bf16 hi/lo per-head layouts (q pre-scaled)
    mma_gemm<0><<<dim3(3 * Cdim / 128, (Bz * Nseq) / 128), 256>>>(x, nullptr);

    // 2) Flash attention (mma.sync) -> g_y
    attn_mma<<<dim3(Nseq / 64, BHn), 128>>>();

    // 3) Output projection -> d_out
    mma_gemm<1><<<dim3(Cdim / 128, (Bz * Nseq) / 128), 256>>>(nullptr, out);
}